// round 7
// baseline (speedup 1.0000x reference)
#include <cuda_runtime.h>

#define N_NODES 100000
#define N_EDGES 1200000
#define D_FEAT  64
#define D_OUT   128
#define SCAN_CHUNK  1024
#define SCAN_BLOCKS ((N_NODES + SCAN_CHUNK - 1) / SCAN_CHUNK)   // 98

// Scratch (no allocs allowed)
__device__ int g_esrc[N_EDGES];                 // src ids binned by dst
__device__ int g_count[N_NODES];
__device__ int g_off[N_NODES + 1];
__device__ int g_cursor[N_NODES];
__device__ int g_bsum[SCAN_BLOCKS];
__device__ int g_bscan[SCAN_BLOCKS];

// ---------------------------------------------------------------------------
// K0: zero per-node counters.
// ---------------------------------------------------------------------------
__global__ void __launch_bounds__(256) init_kernel() {
    int i = blockIdx.x * 256 + threadIdx.x;
    if (i < N_NODES) g_count[i] = 0;
}

// ---------------------------------------------------------------------------
// K1: count edges per dst.
// ---------------------------------------------------------------------------
__global__ void __launch_bounds__(256) count_kernel(const int* __restrict__ dst) {
    int e = blockIdx.x * 256 + threadIdx.x;
    if (e >= N_EDGES) return;
    int d = __ldg(dst + e);
    if ((unsigned)d < N_NODES) atomicAdd(&g_count[d], 1);
}

// ---------------------------------------------------------------------------
// K2a/b/c: two-level exclusive scan of g_count -> g_off / g_cursor.
// ---------------------------------------------------------------------------
__global__ void __launch_bounds__(256) scan_block_sums() {
    __shared__ int sh[256];
    int b = blockIdx.x, tid = threadIdx.x;
    int base = b * SCAN_CHUNK + tid * 4;
    int s = 0;
    #pragma unroll
    for (int j = 0; j < 4; j++) { int i = base + j; if (i < N_NODES) s += g_count[i]; }
    sh[tid] = s; __syncthreads();
    for (int o = 128; o; o >>= 1) { if (tid < o) sh[tid] += sh[tid + o]; __syncthreads(); }
    if (tid == 0) g_bsum[b] = sh[0];
}

__global__ void __launch_bounds__(128) scan_partials() {
    __shared__ int sh[128];
    int tid = threadIdx.x;
    int v = (tid < SCAN_BLOCKS) ? g_bsum[tid] : 0;
    sh[tid] = v; __syncthreads();
    #pragma unroll
    for (int o = 1; o < 128; o <<= 1) {
        int t = (tid >= o) ? sh[tid - o] : 0;
        __syncthreads();
        sh[tid] += t;
        __syncthreads();
    }
    if (tid < SCAN_BLOCKS) g_bscan[tid] = sh[tid] - v;   // exclusive
    if (tid == 127) g_off[N_NODES] = sh[127];            // total
}

__global__ void __launch_bounds__(256) scan_write_offsets() {
    __shared__ int sh[256];
    int b = blockIdx.x, tid = threadIdx.x;
    int base = b * SCAN_CHUNK + tid * 4;
    int c[4]; int s = 0;
    #pragma unroll
    for (int j = 0; j < 4; j++) {
        int i = base + j;
        c[j] = (i < N_NODES) ? g_count[i] : 0;
        s += c[j];
    }
    sh[tid] = s; __syncthreads();
    int v = s;
    #pragma unroll
    for (int o = 1; o < 256; o <<= 1) {
        int t = (tid >= o) ? sh[tid - o] : 0;
        __syncthreads();
        sh[tid] += t;
        __syncthreads();
    }
    int run = g_bscan[b] + (sh[tid] - v);
    #pragma unroll
    for (int j = 0; j < 4; j++) {
        int i = base + j;
        if (i < N_NODES) { g_off[i] = run; g_cursor[i] = run; run += c[j]; }
    }
}

// ---------------------------------------------------------------------------
// K3: bin edges by dst (4B src id only).
// ---------------------------------------------------------------------------
__global__ void __launch_bounds__(256) bin_kernel(
    const int* __restrict__ src, const int* __restrict__ dst)
{
    int e = blockIdx.x * 256 + threadIdx.x;
    if (e >= N_EDGES) return;
    int d = __ldg(dst + e);
    if ((unsigned)d >= N_NODES) return;
    int p = atomicAdd(&g_cursor[d], 1);
    g_esrc[p] = __ldg(src + e);
}

// ---------------------------------------------------------------------------
// K4: FULLY FUSED attention + FC + ReLU.
// Warp owns 8 consecutive nodes, processed as 2 halves of 4:
//   attention (warp-per-node, hk row loaded once, used for dot AND weighted
//   sum; exp without max-shift — scores ~N(0,64), exp fits fp32 trivially)
//   -> rst row staged in SMEM -> 4-node FC block from SMEM (Wt transposed,
//   LDS.128 conflict-free) -> relu -> out.
// Attention warps are LTS-latency bound; FC phases are FFMA bound — the
// scheduler overlaps them across warps. g_rst global round-trip eliminated.
// ---------------------------------------------------------------------------
__device__ __forceinline__ void accum4(float4& acc, const float4 r,
                                       const float4 w0, const float4 w1,
                                       const float4 w2, const float4 w3) {
    acc.x = fmaf(r.x, w0.x, fmaf(r.y, w1.x, fmaf(r.z, w2.x, fmaf(r.w, w3.x, acc.x))));
    acc.y = fmaf(r.x, w0.y, fmaf(r.y, w1.y, fmaf(r.z, w2.y, fmaf(r.w, w3.y, acc.y))));
    acc.z = fmaf(r.x, w0.z, fmaf(r.y, w1.z, fmaf(r.z, w2.z, fmaf(r.w, w3.z, acc.z))));
    acc.w = fmaf(r.x, w0.w, fmaf(r.y, w1.w, fmaf(r.z, w2.w, fmaf(r.w, w3.w, acc.w))));
}

__device__ __forceinline__ float4 relu4(float4 v) {
    v.x = fmaxf(v.x, 0.f); v.y = fmaxf(v.y, 0.f);
    v.z = fmaxf(v.z, 0.f); v.w = fmaxf(v.w, 0.f);
    return v;
}

__global__ void __launch_bounds__(256) attn_fc_kernel(
    const float* __restrict__ hk, const float* __restrict__ hu,
    const float* __restrict__ W, const float* __restrict__ b,
    float* __restrict__ out)
{
    // [0, 8192): Wt[k*128+j]   [8192, 10240): rst staging, 8 warps x 4 nodes x 64
    __shared__ float sh[10240];                         // 40 KB
    float* Wt = sh;
    int tid = threadIdx.x;
    // Write-coalesced transpose staging (old version had 32-way STS conflicts).
    for (int i = tid; i < D_FEAT * D_OUT; i += 256) {
        int k = i >> 7;           // input feat
        int j = i & 127;          // output feat
        Wt[i] = __ldg(W + j * D_FEAT + k);
    }
    __syncthreads();

    int wid = tid >> 5, lane = tid & 31;
    float* srst = sh + 8192 + wid * 256;                // 4 nodes x 64 feats
    const float2* hk2 = (const float2*)hk;
    const float4* Wt4 = (const float4*)Wt;
    const float4* srst4 = (const float4*)srst;
    float4* out4 = (float4*)out;
    float4 bb = __ldg((const float4*)b + lane);

    int nbase = (blockIdx.x * 8 + wid) * 8;             // 8 nodes per warp

    #pragma unroll
    for (int half = 0; half < 2; half++) {
        int hbase = nbase + half * 4;

        // ---- attention for 4 nodes ----
        for (int m = 0; m < 4; m++) {
            int node = hbase + m;
            if (node >= N_NODES) break;
            float2 u = __ldg((const float2*)hu + (size_t)node * 32 + lane);
            int beg = g_off[node], end = g_off[node + 1];
            float ax = 0.f, ay = 0.f, denom = 0.f;
            for (int base = beg; base < end; base += 32) {
                int n = min(32, end - base);
                int srcid = (lane < n) ? __ldg(&g_esrc[base + lane]) : 0;
                int j = 0;
                for (; j + 2 <= n; j += 2) {
                    int s0 = __shfl_sync(0xffffffffu, srcid, j);
                    int s1 = __shfl_sync(0xffffffffu, srcid, j + 1);
                    float2 a0 = __ldg(hk2 + (size_t)s0 * 32 + lane);
                    float2 a1 = __ldg(hk2 + (size_t)s1 * 32 + lane);
                    float p0 = a0.x * u.x + a0.y * u.y;
                    float p1 = a1.x * u.x + a1.y * u.y;
                    #pragma unroll
                    for (int o = 16; o; o >>= 1) {
                        p0 += __shfl_xor_sync(0xffffffffu, p0, o);
                        p1 += __shfl_xor_sync(0xffffffffu, p1, o);
                    }
                    float e0 = __expf(p0);
                    float e1 = __expf(p1);
                    ax = fmaf(e0, a0.x, fmaf(e1, a1.x, ax));
                    ay = fmaf(e0, a0.y, fmaf(e1, a1.y, ay));
                    denom += e0 + e1;
                }
                if (j < n) {
                    int s0 = __shfl_sync(0xffffffffu, srcid, j);
                    float2 a0 = __ldg(hk2 + (size_t)s0 * 32 + lane);
                    float p0 = a0.x * u.x + a0.y * u.y;
                    #pragma unroll
                    for (int o = 16; o; o >>= 1) p0 += __shfl_xor_sync(0xffffffffu, p0, o);
                    float e0 = __expf(p0);
                    ax = fmaf(e0, a0.x, ax);
                    ay = fmaf(e0, a0.y, ay);
                    denom += e0;
                }
            }
            float inv = (end > beg) ? 1.f / denom : 0.f;     // deg==0 -> zero row
            ((float2*)srst)[m * 32 + lane] = make_float2(ax * inv, ay * inv);
        }
        __syncwarp();   // staging visible across lanes before FC reads

        // ---- FC + relu for these 4 nodes ----
        if (hbase < N_NODES) {
            float4 a0 = bb, a1 = bb, a2 = bb, a3 = bb;
            #pragma unroll 4
            for (int kc4 = 0; kc4 < 16; kc4++) {
                float4 w0 = Wt4[(kc4 * 4 + 0) * 32 + lane];
                float4 w1 = Wt4[(kc4 * 4 + 1) * 32 + lane];
                float4 w2 = Wt4[(kc4 * 4 + 2) * 32 + lane];
                float4 w3 = Wt4[(kc4 * 4 + 3) * 32 + lane];
                float4 r0 = srst4[0 * 16 + kc4];
                float4 r1 = srst4[1 * 16 + kc4];
                float4 r2 = srst4[2 * 16 + kc4];
                float4 r3 = srst4[3 * 16 + kc4];
                accum4(a0, r0, w0, w1, w2, w3);
                accum4(a1, r1, w0, w1, w2, w3);
                accum4(a2, r2, w0, w1, w2, w3);
                accum4(a3, r3, w0, w1, w2, w3);
            }
            if (hbase + 0 < N_NODES) out4[(size_t)(hbase + 0) * 32 + lane] = relu4(a0);
            if (hbase + 1 < N_NODES) out4[(size_t)(hbase + 1) * 32 + lane] = relu4(a1);
            if (hbase + 2 < N_NODES) out4[(size_t)(hbase + 2) * 32 + lane] = relu4(a2);
            if (hbase + 3 < N_NODES) out4[(size_t)(hbase + 3) * 32 + lane] = relu4(a3);
        }
        __syncwarp();   // FC reads done before next half overwrites staging
    }
}

// ---------------------------------------------------------------------------
// Inputs: hk[f32 N*64], hu[f32 N*64], W[f32 128*64], b[f32 128],
//         src[i32 E], dst[i32 E].  Output: f32 N*128.
// ---------------------------------------------------------------------------
extern "C" void kernel_launch(void* const* d_in, const int* in_sizes, int n_in,
                              void* d_out, int out_size) {
    const float* hk  = (const float*)d_in[0];
    const float* hu  = (const float*)d_in[1];
    const float* W   = (const float*)d_in[2];
    const float* b   = (const float*)d_in[3];
    const int*   src = (const int*)d_in[4];
    const int*   dst = (const int*)d_in[5];
    float* out = (float*)d_out;

    init_kernel<<<(N_NODES + 255) / 256, 256>>>();
    count_kernel<<<(N_EDGES + 255) / 256, 256>>>(dst);
    scan_block_sums<<<SCAN_BLOCKS, 256>>>();
    scan_partials<<<1, 128>>>();
    scan_write_offsets<<<SCAN_BLOCKS, 256>>>();
    bin_kernel<<<(N_EDGES + 255) / 256, 256>>>(src, dst);
    // 8 warps/block, 8 nodes/warp -> 64 nodes/block
    attn_fc_kernel<<<(N_NODES + 63) / 64, 256>>>(hk, hu, W, b, out);
}

// round 8
// speedup vs baseline: 1.1490x; 1.1490x over previous
#include <cuda_runtime.h>

#define N_NODES 100000
#define N_EDGES 1200000
#define D_FEAT  64
#define D_OUT   128
#define SCAN_CHUNK  1024
#define SCAN_BLOCKS ((N_NODES + SCAN_CHUNK - 1) / SCAN_CHUNK)   // 98

// Scratch (no allocs allowed)
__device__ int g_esrc[N_EDGES];                 // src ids binned by dst
__device__ int g_count[N_NODES];
__device__ int g_off[N_NODES + 1];
__device__ int g_cursor[N_NODES];
__device__ int g_bsum[SCAN_BLOCKS];
__device__ int g_bscan[SCAN_BLOCKS];
__device__ int g_arrive;
__device__ int g_release;

// ---------------------------------------------------------------------------
// K0: zero per-node counters + reset scan handshake flags (graph replays!).
// ---------------------------------------------------------------------------
__global__ void __launch_bounds__(256) init_kernel() {
    int i = blockIdx.x * 256 + threadIdx.x;
    if (i < N_NODES) g_count[i] = 0;
    if (i == 0) { g_arrive = 0; g_release = 0; }
}

// ---------------------------------------------------------------------------
// K1: count edges per dst.
// ---------------------------------------------------------------------------
__global__ void __launch_bounds__(256) count_kernel(const int* __restrict__ dst) {
    int e = blockIdx.x * 256 + threadIdx.x;
    if (e >= N_EDGES) return;
    int d = __ldg(dst + e);
    if ((unsigned)d < N_NODES) atomicAdd(&g_count[d], 1);
}

// ---------------------------------------------------------------------------
// K2: single-kernel two-level exclusive scan (was 3 kernels; saves 2 launch
// boundaries). Arrival counter + release flag; arrival is non-blocking so
// there is no residency deadlock; flags reset by init each replay.
// ---------------------------------------------------------------------------
__global__ void __launch_bounds__(256) scan_fused_kernel() {
    __shared__ int sh[256];
    __shared__ int sp[128];
    __shared__ int s_last;
    int b = blockIdx.x, tid = threadIdx.x;
    int base = b * SCAN_CHUNK + tid * 4;

    // phase A: per-block sum
    int c[4]; int s = 0;
    #pragma unroll
    for (int j = 0; j < 4; j++) {
        int i = base + j;
        c[j] = (i < N_NODES) ? g_count[i] : 0;
        s += c[j];
    }
    sh[tid] = s; __syncthreads();
    for (int o = 128; o; o >>= 1) { if (tid < o) sh[tid] += sh[tid + o]; __syncthreads(); }
    if (tid == 0) {
        g_bsum[b] = sh[0];
        __threadfence();
        s_last = (atomicAdd(&g_arrive, 1) == SCAN_BLOCKS - 1);
    }
    __syncthreads();

    // phase B: last-arriving block scans the 98 block sums
    if (s_last) {
        int v = (tid < SCAN_BLOCKS) ? g_bsum[tid] : 0;
        if (tid < 128) sp[tid] = v;
        __syncthreads();
        #pragma unroll
        for (int o = 1; o < 128; o <<= 1) {
            int t = (tid < 128 && tid >= o) ? sp[tid - o] : 0;
            __syncthreads();
            if (tid < 128) sp[tid] += t;
            __syncthreads();
        }
        if (tid < SCAN_BLOCKS) g_bscan[tid] = sp[tid] - v;   // exclusive
        if (tid == 127) g_off[N_NODES] = sp[127];            // total
        __threadfence();
        __syncthreads();
        if (tid == 0) atomicExch(&g_release, 1);
    }

    // phase C: wait for global prefix, then write offsets
    if (tid == 0) while (atomicAdd(&g_release, 0) == 0) {}
    __syncthreads();

    sh[tid] = s; __syncthreads();
    int v2 = s;
    #pragma unroll
    for (int o = 1; o < 256; o <<= 1) {
        int t = (tid >= o) ? sh[tid - o] : 0;
        __syncthreads();
        sh[tid] += t;
        __syncthreads();
    }
    int run = g_bscan[b] + (sh[tid] - v2);
    #pragma unroll
    for (int j = 0; j < 4; j++) {
        int i = base + j;
        if (i < N_NODES) { g_off[i] = run; g_cursor[i] = run; run += c[j]; }
    }
}

// ---------------------------------------------------------------------------
// K3: bin edges by dst (4B src id only).
// ---------------------------------------------------------------------------
__global__ void __launch_bounds__(256) bin_kernel(
    const int* __restrict__ src, const int* __restrict__ dst)
{
    int e = blockIdx.x * 256 + threadIdx.x;
    if (e >= N_EDGES) return;
    int d = __ldg(dst + e);
    if ((unsigned)d >= N_NODES) return;
    int p = atomicAdd(&g_cursor[d], 1);
    g_esrc[p] = __ldg(src + e);
}

// ---------------------------------------------------------------------------
// K4: FUSED attention + FC, half-warp edition.
// Warp = two independent 16-lane halves; each half owns 4 nodes, lane holds
// float4 (4 feats). Per edge: one coalesced 256B hk row, dot reduced in 4
// shuffles (width=16), exp (max-shift provably unneeded), accumulate.
// 2-edge unroll x 2 halves = 4 independent latency chains per warp (vs 2 in
// R7 whose overlap attempt was NEUTRAL -> chain latency is the binding
// constraint). Staged rst -> two 4-node FC blocks from smem -> relu -> out.
// ---------------------------------------------------------------------------
__device__ __forceinline__ void accum4(float4& acc, const float4 r,
                                       const float4 w0, const float4 w1,
                                       const float4 w2, const float4 w3) {
    acc.x = fmaf(r.x, w0.x, fmaf(r.y, w1.x, fmaf(r.z, w2.x, fmaf(r.w, w3.x, acc.x))));
    acc.y = fmaf(r.x, w0.y, fmaf(r.y, w1.y, fmaf(r.z, w2.y, fmaf(r.w, w3.y, acc.y))));
    acc.z = fmaf(r.x, w0.z, fmaf(r.y, w1.z, fmaf(r.z, w2.z, fmaf(r.w, w3.z, acc.z))));
    acc.w = fmaf(r.x, w0.w, fmaf(r.y, w1.w, fmaf(r.z, w2.w, fmaf(r.w, w3.w, acc.w))));
}

__device__ __forceinline__ float4 relu4(float4 v) {
    v.x = fmaxf(v.x, 0.f); v.y = fmaxf(v.y, 0.f);
    v.z = fmaxf(v.z, 0.f); v.w = fmaxf(v.w, 0.f);
    return v;
}

__device__ __forceinline__ float dot4(const float4 a, const float4 u) {
    return fmaf(a.x, u.x, fmaf(a.y, u.y, fmaf(a.z, u.z, a.w * u.w)));
}

__global__ void __launch_bounds__(256) attn_fc_kernel(
    const float* __restrict__ hk, const float* __restrict__ hu,
    const float* __restrict__ W, const float* __restrict__ b,
    float* __restrict__ out)
{
    // [0,8192): Wt[k*128+j];  [8192,12288): staging 8 warps x 8 nodes x 64
    __shared__ float sh[12288];                          // 48 KB
    float* Wt = sh;
    int tid = threadIdx.x;
    for (int i = tid; i < D_FEAT * D_OUT; i += 256) {
        int k = i >> 7;            // input feat
        int j = i & 127;           // output feat
        Wt[i] = __ldg(W + j * D_FEAT + k);               // coalesced STS
    }
    __syncthreads();

    int wid = tid >> 5, lane = tid & 31;
    int half = lane >> 4, hl = lane & 15;
    unsigned hm = half ? 0xFFFF0000u : 0x0000FFFFu;
    float* stage = sh + 8192 + wid * 512;                // 8 nodes x 64 feats
    float4* stage4 = (float4*)stage;
    const float4* hk4 = (const float4*)hk;
    const float4* Wt4 = (const float4*)Wt;
    float4* out4 = (float4*)out;
    float4 bb = __ldg((const float4*)b + lane);

    int nbase = (blockIdx.x * 8 + wid) * 8;              // 8 nodes per warp
    int hbase = nbase + half * 4;                        // 4 per half-warp

    // ---- attention: each half-warp processes its 4 nodes ----
    for (int m = 0; m < 4; m++) {
        int node = hbase + m;
        if (node >= N_NODES) break;
        float4 u = __ldg((const float4*)hu + (size_t)node * 16 + hl);
        int beg = __ldg(&g_off[node]), end = __ldg(&g_off[node + 1]);
        float4 acc = make_float4(0.f, 0.f, 0.f, 0.f);
        float denom = 0.f;

        for (int base = beg; base < end; base += 16) {
            int n = min(16, end - base);
            int srcid = (hl < n) ? __ldg(&g_esrc[base + hl]) : 0;
            int j = 0;
            for (; j + 2 <= n; j += 2) {
                int s0 = __shfl_sync(hm, srcid, j, 16);
                int s1 = __shfl_sync(hm, srcid, j + 1, 16);
                float4 a0 = __ldg(hk4 + (size_t)s0 * 16 + hl);
                float4 a1 = __ldg(hk4 + (size_t)s1 * 16 + hl);
                float p0 = dot4(a0, u);
                float p1 = dot4(a1, u);
                #pragma unroll
                for (int o = 8; o; o >>= 1) {
                    p0 += __shfl_xor_sync(hm, p0, o, 16);
                    p1 += __shfl_xor_sync(hm, p1, o, 16);
                }
                float e0 = __expf(p0);
                float e1 = __expf(p1);
                acc.x = fmaf(e0, a0.x, fmaf(e1, a1.x, acc.x));
                acc.y = fmaf(e0, a0.y, fmaf(e1, a1.y, acc.y));
                acc.z = fmaf(e0, a0.z, fmaf(e1, a1.z, acc.z));
                acc.w = fmaf(e0, a0.w, fmaf(e1, a1.w, acc.w));
                denom += e0 + e1;
            }
            if (j < n) {
                int s0 = __shfl_sync(hm, srcid, j, 16);
                float4 a0 = __ldg(hk4 + (size_t)s0 * 16 + hl);
                float p0 = dot4(a0, u);
                #pragma unroll
                for (int o = 8; o; o >>= 1) p0 += __shfl_xor_sync(hm, p0, o, 16);
                float e0 = __expf(p0);
                acc.x = fmaf(e0, a0.x, acc.x);
                acc.y = fmaf(e0, a0.y, acc.y);
                acc.z = fmaf(e0, a0.z, acc.z);
                acc.w = fmaf(e0, a0.w, acc.w);
                denom += e0;
            }
        }
        float inv = (end > beg) ? 1.f / denom : 0.f;     // deg==0 -> zero row
        stage4[(half * 4 + m) * 16 + hl] =
            make_float4(acc.x * inv, acc.y * inv, acc.z * inv, acc.w * inv);
    }
    __syncwarp();   // both halves' staging visible before full-warp FC

    // ---- FC + relu: two 4-node groups (keeps regs for occupancy) ----
    #pragma unroll
    for (int g = 0; g < 2; g++) {
        int gbase = nbase + g * 4;
        if (gbase >= N_NODES) break;
        float4 a0 = bb, a1 = bb, a2 = bb, a3 = bb;
        #pragma unroll 4
        for (int kc4 = 0; kc4 < 16; kc4++) {
            float4 w0 = Wt4[(kc4 * 4 + 0) * 32 + lane];
            float4 w1 = Wt4[(kc4 * 4 + 1) * 32 + lane];
            float4 w2 = Wt4[(kc4 * 4 + 2) * 32 + lane];
            float4 w3 = Wt4[(kc4 * 4 + 3) * 32 + lane];
            float4 r0 = stage4[(g * 4 + 0) * 16 + kc4];
            float4 r1 = stage4[(g * 4 + 1) * 16 + kc4];
            float4 r2 = stage4[(g * 4 + 2) * 16 + kc4];
            float4 r3 = stage4[(g * 4 + 3) * 16 + kc4];
            accum4(a0, r0, w0, w1, w2, w3);
            accum4(a1, r1, w0, w1, w2, w3);
            accum4(a2, r2, w0, w1, w2, w3);
            accum4(a3, r3, w0, w1, w2, w3);
        }
        if (gbase + 0 < N_NODES) out4[(size_t)(gbase + 0) * 32 + lane] = relu4(a0);
        if (gbase + 1 < N_NODES) out4[(size_t)(gbase + 1) * 32 + lane] = relu4(a1);
        if (gbase + 2 < N_NODES) out4[(size_t)(gbase + 2) * 32 + lane] = relu4(a2);
        if (gbase + 3 < N_NODES) out4[(size_t)(gbase + 3) * 32 + lane] = relu4(a3);
    }
}

// ---------------------------------------------------------------------------
// Inputs: hk[f32 N*64], hu[f32 N*64], W[f32 128*64], b[f32 128],
//         src[i32 E], dst[i32 E].  Output: f32 N*128.
// ---------------------------------------------------------------------------
extern "C" void kernel_launch(void* const* d_in, const int* in_sizes, int n_in,
                              void* d_out, int out_size) {
    const float* hk  = (const float*)d_in[0];
    const float* hu  = (const float*)d_in[1];
    const float* W   = (const float*)d_in[2];
    const float* b   = (const float*)d_in[3];
    const int*   src = (const int*)d_in[4];
    const int*   dst = (const int*)d_in[5];
    float* out = (float*)d_out;

    init_kernel<<<(N_NODES + 255) / 256, 256>>>();
    count_kernel<<<(N_EDGES + 255) / 256, 256>>>(dst);
    scan_fused_kernel<<<SCAN_BLOCKS, 256>>>();
    bin_kernel<<<(N_EDGES + 255) / 256, 256>>>(src, dst);
    attn_fc_kernel<<<(N_NODES + 63) / 64, 256>>>(hk, hu, W, b, out);
}

// round 9
// speedup vs baseline: 1.1893x; 1.0351x over previous
#include <cuda_runtime.h>

#define N_NODES 100000
#define N_EDGES 1200000
#define D_FEAT  64
#define D_OUT   128
#define SCAN_CHUNK  1024
#define SCAN_BLOCKS ((N_NODES + SCAN_CHUNK - 1) / SCAN_CHUNK)   // 98

// Scratch (no allocs allowed)
__device__ int g_esrc[N_EDGES];                 // src ids binned by dst
__device__ int g_rank[N_EDGES];                 // per-edge rank within its dst bin
__device__ int g_count[N_NODES];
__device__ int g_off[N_NODES + 1];
__device__ int g_bsum[SCAN_BLOCKS];
__device__ int g_bscan[SCAN_BLOCKS];
__device__ int g_arrive;
__device__ int g_release;

// ---------------------------------------------------------------------------
// K0: zero per-node counters + reset scan handshake flags (graph replays!).
// ---------------------------------------------------------------------------
__global__ void __launch_bounds__(256) init_kernel() {
    int i = blockIdx.x * 256 + threadIdx.x;
    if (i < N_NODES) g_count[i] = 0;
    if (i == 0) { g_arrive = 0; g_release = 0; }
}

// ---------------------------------------------------------------------------
// K1: count edges per dst AND record each edge's rank (atomic return value).
// The rank makes bin_kernel atomic-free (R8 profile: bin was atomic-latency
// bound, issue=4.5%).
// ---------------------------------------------------------------------------
__global__ void __launch_bounds__(256) count_kernel(const int* __restrict__ dst) {
    int e = blockIdx.x * 256 + threadIdx.x;
    if (e >= N_EDGES) return;
    int d = __ldg(dst + e);
    int r = ((unsigned)d < N_NODES) ? atomicAdd(&g_count[d], 1) : 0;
    g_rank[e] = r;                                   // coalesced
}

// ---------------------------------------------------------------------------
// K2: single-kernel two-level exclusive scan (arrival counter + release flag;
// arrival is non-blocking -> no residency deadlock; flags reset each replay).
// ---------------------------------------------------------------------------
__global__ void __launch_bounds__(256) scan_fused_kernel() {
    __shared__ int sh[256];
    __shared__ int sp[128];
    __shared__ int s_last;
    int b = blockIdx.x, tid = threadIdx.x;
    int base = b * SCAN_CHUNK + tid * 4;

    int c[4]; int s = 0;
    #pragma unroll
    for (int j = 0; j < 4; j++) {
        int i = base + j;
        c[j] = (i < N_NODES) ? g_count[i] : 0;
        s += c[j];
    }
    sh[tid] = s; __syncthreads();
    for (int o = 128; o; o >>= 1) { if (tid < o) sh[tid] += sh[tid + o]; __syncthreads(); }
    if (tid == 0) {
        g_bsum[b] = sh[0];
        __threadfence();
        s_last = (atomicAdd(&g_arrive, 1) == SCAN_BLOCKS - 1);
    }
    __syncthreads();

    if (s_last) {
        int v = (tid < SCAN_BLOCKS) ? g_bsum[tid] : 0;
        if (tid < 128) sp[tid] = v;
        __syncthreads();
        #pragma unroll
        for (int o = 1; o < 128; o <<= 1) {
            int t = (tid < 128 && tid >= o) ? sp[tid - o] : 0;
            __syncthreads();
            if (tid < 128) sp[tid] += t;
            __syncthreads();
        }
        if (tid < SCAN_BLOCKS) g_bscan[tid] = sp[tid] - v;   // exclusive
        if (tid == 127) g_off[N_NODES] = sp[127];            // total
        __threadfence();
        __syncthreads();
        if (tid == 0) atomicExch(&g_release, 1);
    }

    if (tid == 0) while (atomicAdd(&g_release, 0) == 0) {}
    __syncthreads();

    sh[tid] = s; __syncthreads();
    int v2 = s;
    #pragma unroll
    for (int o = 1; o < 256; o <<= 1) {
        int t = (tid >= o) ? sh[tid - o] : 0;
        __syncthreads();
        sh[tid] += t;
        __syncthreads();
    }
    int run = g_bscan[b] + (sh[tid] - v2);
    #pragma unroll
    for (int j = 0; j < 4; j++) {
        int i = base + j;
        if (i < N_NODES) { g_off[i] = run; run += c[j]; }
    }
}

// ---------------------------------------------------------------------------
// K3: bin edges by dst — NO atomics: slot = off[dst] + rank.
// ---------------------------------------------------------------------------
__global__ void __launch_bounds__(256) bin_kernel(
    const int* __restrict__ src, const int* __restrict__ dst)
{
    int e = blockIdx.x * 256 + threadIdx.x;
    if (e >= N_EDGES) return;
    int d = __ldg(dst + e);
    if ((unsigned)d >= N_NODES) return;
    g_esrc[__ldg(&g_off[d]) + __ldg(&g_rank[e])] = __ldg(src + e);
}

// ---------------------------------------------------------------------------
// K4: FUSED attention + FC, half-warp + SOFTWARE-PIPELINED loads.
// Each 16-lane half owns 4 nodes; lane holds float4 (4 feats). Per edge:
// one coalesced 256B hk row used for dot AND weighted sum; dot reduced in
// 4 shuffles (width=16); exp without max-shift (scores ~N(0,64), fp32-safe).
// Pipeline: prefetch next edge pair's hk rows before reducing current pair —
// overlaps ~300cyc L2 latency with the shuffle/exp/FMA block (R7/R8 showed
// chain latency, not issue bandwidth, binds).
// ---------------------------------------------------------------------------
__device__ __forceinline__ void accum4(float4& acc, const float4 r,
                                       const float4 w0, const float4 w1,
                                       const float4 w2, const float4 w3) {
    acc.x = fmaf(r.x, w0.x, fmaf(r.y, w1.x, fmaf(r.z, w2.x, fmaf(r.w, w3.x, acc.x))));
    acc.y = fmaf(r.x, w0.y, fmaf(r.y, w1.y, fmaf(r.z, w2.y, fmaf(r.w, w3.y, acc.y))));
    acc.z = fmaf(r.x, w0.z, fmaf(r.y, w1.z, fmaf(r.z, w2.z, fmaf(r.w, w3.z, acc.z))));
    acc.w = fmaf(r.x, w0.w, fmaf(r.y, w1.w, fmaf(r.z, w2.w, fmaf(r.w, w3.w, acc.w))));
}

__device__ __forceinline__ float4 relu4(float4 v) {
    v.x = fmaxf(v.x, 0.f); v.y = fmaxf(v.y, 0.f);
    v.z = fmaxf(v.z, 0.f); v.w = fmaxf(v.w, 0.f);
    return v;
}

__device__ __forceinline__ float dot4(const float4 a, const float4 u) {
    return fmaf(a.x, u.x, fmaf(a.y, u.y, fmaf(a.z, u.z, a.w * u.w)));
}

__global__ void __launch_bounds__(256) attn_fc_kernel(
    const float* __restrict__ hk, const float* __restrict__ hu,
    const float* __restrict__ W, const float* __restrict__ b,
    float* __restrict__ out)
{
    // [0,8192): Wt[k*128+j];  [8192,12288): staging 8 warps x 8 nodes x 64
    __shared__ float sh[12288];                          // 48 KB
    float* Wt = sh;
    int tid = threadIdx.x;
    for (int i = tid; i < D_FEAT * D_OUT; i += 256) {
        int k = i >> 7;            // input feat
        int j = i & 127;           // output feat
        Wt[i] = __ldg(W + j * D_FEAT + k);               // coalesced STS
    }
    __syncthreads();

    int wid = tid >> 5, lane = tid & 31;
    int half = lane >> 4, hl = lane & 15;
    unsigned hm = half ? 0xFFFF0000u : 0x0000FFFFu;
    float* stage = sh + 8192 + wid * 512;                // 8 nodes x 64 feats
    float4* stage4 = (float4*)stage;
    const float4* hk4 = (const float4*)hk;
    const float4* Wt4 = (const float4*)Wt;
    float4* out4 = (float4*)out;
    float4 bb = __ldg((const float4*)b + lane);

    int nbase = (blockIdx.x * 8 + wid) * 8;              // 8 nodes per warp
    int hbase = nbase + half * 4;                        // 4 per half-warp

    // ---- attention: each half-warp processes its 4 nodes ----
    for (int m = 0; m < 4; m++) {
        int node = hbase + m;
        if (node >= N_NODES) break;
        float4 u = __ldg((const float4*)hu + (size_t)node * 16 + hl);
        int beg = __ldg(&g_off[node]), end = __ldg(&g_off[node + 1]);
        float4 acc = make_float4(0.f, 0.f, 0.f, 0.f);
        float denom = 0.f;

        for (int base = beg; base < end; base += 16) {
            int n = min(16, end - base);
            int srcid = (hl < n) ? __ldg(&g_esrc[base + hl]) : 0;

            // prime the pipeline with the first pair
            float4 a0, a1;
            {
                int s0 = __shfl_sync(hm, srcid, 0, 16);
                a0 = __ldg(hk4 + (size_t)s0 * 16 + hl);
                if (n >= 2) {
                    int s1 = __shfl_sync(hm, srcid, 1, 16);
                    a1 = __ldg(hk4 + (size_t)s1 * 16 + hl);
                }
            }
            int j = 0;
            for (; j + 2 <= n; j += 2) {
                float4 c0 = a0, c1 = a1;
                // prefetch next pair BEFORE the dependent reduce chain
                if (j + 4 <= n) {
                    int t0 = __shfl_sync(hm, srcid, j + 2, 16);
                    int t1 = __shfl_sync(hm, srcid, j + 3, 16);
                    a0 = __ldg(hk4 + (size_t)t0 * 16 + hl);
                    a1 = __ldg(hk4 + (size_t)t1 * 16 + hl);
                } else if (j + 3 == n) {
                    int t0 = __shfl_sync(hm, srcid, j + 2, 16);
                    a0 = __ldg(hk4 + (size_t)t0 * 16 + hl);
                }
                float p0 = dot4(c0, u);
                float p1 = dot4(c1, u);
                #pragma unroll
                for (int o = 8; o; o >>= 1) {
                    p0 += __shfl_xor_sync(hm, p0, o, 16);
                    p1 += __shfl_xor_sync(hm, p1, o, 16);
                }
                float e0 = __expf(p0);
                float e1 = __expf(p1);
                acc.x = fmaf(e0, c0.x, fmaf(e1, c1.x, acc.x));
                acc.y = fmaf(e0, c0.y, fmaf(e1, c1.y, acc.y));
                acc.z = fmaf(e0, c0.z, fmaf(e1, c1.z, acc.z));
                acc.w = fmaf(e0, c0.w, fmaf(e1, c1.w, acc.w));
                denom += e0 + e1;
            }
            if (j < n) {                     // odd tail: row already in a0
                float p0 = dot4(a0, u);
                #pragma unroll
                for (int o = 8; o; o >>= 1) p0 += __shfl_xor_sync(hm, p0, o, 16);
                float e0 = __expf(p0);
                acc.x = fmaf(e0, a0.x, acc.x);
                acc.y = fmaf(e0, a0.y, acc.y);
                acc.z = fmaf(e0, a0.z, acc.z);
                acc.w = fmaf(e0, a0.w, acc.w);
                denom += e0;
            }
        }
        float inv = (end > beg) ? 1.f / denom : 0.f;     // deg==0 -> zero row
        stage4[(half * 4 + m) * 16 + hl] =
            make_float4(acc.x * inv, acc.y * inv, acc.z * inv, acc.w * inv);
    }
    __syncwarp();   // both halves' staging visible before full-warp FC

    // ---- FC + relu: two 4-node groups ----
    #pragma unroll
    for (int g = 0; g < 2; g++) {
        int gbase = nbase + g * 4;
        if (gbase >= N_NODES) break;
        float4 a0 = bb, a1 = bb, a2 = bb, a3 = bb;
        #pragma unroll 4
        for (int kc4 = 0; kc4 < 16; kc4++) {
            float4 w0 = Wt4[(kc4 * 4 + 0) * 32 + lane];
            float4 w1 = Wt4[(kc4 * 4 + 1) * 32 + lane];
            float4 w2 = Wt4[(kc4 * 4 + 2) * 32 + lane];
            float4 w3 = Wt4[(kc4 * 4 + 3) * 32 + lane];
            float4 r0 = stage4[(g * 4 + 0) * 16 + kc4];
            float4 r1 = stage4[(g * 4 + 1) * 16 + kc4];
            float4 r2 = stage4[(g * 4 + 2) * 16 + kc4];
            float4 r3 = stage4[(g * 4 + 3) * 16 + kc4];
            accum4(a0, r0, w0, w1, w2, w3);
            accum4(a1, r1, w0, w1, w2, w3);
            accum4(a2, r2, w0, w1, w2, w3);
            accum4(a3, r3, w0, w1, w2, w3);
        }
        if (gbase + 0 < N_NODES) out4[(size_t)(gbase + 0) * 32 + lane] = relu4(a0);
        if (gbase + 1 < N_NODES) out4[(size_t)(gbase + 1) * 32 + lane] = relu4(a1);
        if (gbase + 2 < N_NODES) out4[(size_t)(gbase + 2) * 32 + lane] = relu4(a2);
        if (gbase + 3 < N_NODES) out4[(size_t)(gbase + 3) * 32 + lane] = relu4(a3);
    }
}

// ---------------------------------------------------------------------------
// Inputs: hk[f32 N*64], hu[f32 N*64], W[f32 128*64], b[f32 128],
//         src[i32 E], dst[i32 E].  Output: f32 N*128.
// ---------------------------------------------------------------------------
extern "C" void kernel_launch(void* const* d_in, const int* in_sizes, int n_in,
                              void* d_out, int out_size) {
    const float* hk  = (const float*)d_in[0];
    const float* hu  = (const float*)d_in[1];
    const float* W   = (const float*)d_in[2];
    const float* b   = (const float*)d_in[3];
    const int*   src = (const int*)d_in[4];
    const int*   dst = (const int*)d_in[5];
    float* out = (float*)d_out;

    init_kernel<<<(N_NODES + 255) / 256, 256>>>();
    count_kernel<<<(N_EDGES + 255) / 256, 256>>>(dst);
    scan_fused_kernel<<<SCAN_BLOCKS, 256>>>();
    bin_kernel<<<(N_EDGES + 255) / 256, 256>>>(src, dst);
    attn_fc_kernel<<<(N_NODES + 63) / 64, 256>>>(hk, hu, W, b, out);
}